// round 13
// baseline (speedup 1.0000x reference)
#include <cuda_runtime.h>

// Problem constants
#define B_   1024
#define I_   256
#define J_   256
#define K_   64

// Tiling
#define TB   64            // b per CTA
#define TJ   128           // j per CTA (4 floats per lane, LDG.128 rows)
#define ISPL 8             // i-splits (keeps grid at 256 CTAs)
#define IPC  (I_ / ISPL)   // 32 iterations per CTA
#define NTHR 512           // 16 warps, 4 b per warp
#define BPW  4
#define NBT  (B_ / TB)     // 16
#define NJT  (J_ / TJ)     // 2

#define TILE_FLOATS (K_ * TJ)          // 8192 floats = 32 KB per (i, jt) tile
#define TILE_BYTES  (TILE_FLOATS * 4)

// Static device scratch (no allocations allowed)
// Yt is tile-contiguous: [i][jt][k][TJ]  (each (i,jt) tile = 32KB block)
__device__ float        g_Yt[I_ * K_ * J_];             // 16.8 MB
__device__ int4         g_prep[I_ * B_];                // [i][b]: {w0,w1,off0B,off1B} (jt-independent)
__device__ float4       g_part4[ISPL * B_ * J_ / 4];    // i-split partials (8 MB)
__device__ unsigned int g_cnt[NBT * NJT];               // last-block counters (self-resetting)

#define NT_BLOCKS (I_ * (J_ / 32) * (K_ / 32))          // 4096 transpose blocks
#define NP_BLOCKS ((B_ / 64) * (I_ / 64))               // 64 prep blocks

// ---------------------------------------------------------------------------
// pre_kernel: fused Y-transpose + interval/weight prep (disjoint block ranges
// run concurrently). Transpose writes the tile-contiguous layout:
//   Yt[i][jt][k][jl]  with jt = j>>7, jl = j&127.
// Prep offsets are byte offsets WITHOUT the jt term:
//   off0 = (i*K*J + k*TJ)*4 ; consumer folds jt*TILE_BYTES into its base.
// ---------------------------------------------------------------------------
__global__ void __launch_bounds__(256) pre_kernel(const float* __restrict__ x,
                                                  const float* __restrict__ Xg,
                                                  const float* __restrict__ Y) {
    const int bid = blockIdx.x;
    const int tid = threadIdx.x;

    if (bid < NT_BLOCKS) {
        // ---- transpose Y[i][j][k] -> Yt[i][jt][k][jl], one 32x32 tile ----
        __shared__ float s[32][33];
        const int i    = bid >> 4;
        const int rest = bid & 15;
        const int jb   = (rest >> 1) * 32;    // 0,32,...,224
        const int kb   = (rest & 1) * 32;     // 0 or 32
        const float* src = Y + (size_t)i * (J_ * K_);

        int jj = tid >> 3, kq = (tid & 7) << 2;
        float4 v = *(const float4*)(src + (size_t)(jb + jj) * K_ + kb + kq);
        s[jj][kq + 0] = v.x; s[jj][kq + 1] = v.y;
        s[jj][kq + 2] = v.z; s[jj][kq + 3] = v.w;
        __syncthreads();

        int k = tid >> 3, jq = (tid & 7) << 2;
        float4 o = make_float4(s[jq + 0][k], s[jq + 1][k], s[jq + 2][k], s[jq + 3][k]);
        const int jt_  = jb >> 7;             // which 128-j tile
        const int jbin = jb & 127;            // j offset within tile
        *(float4*)(g_Yt + (size_t)i * (K_ * J_) + (size_t)jt_ * TILE_FLOATS
                   + (size_t)(kb + k) * TJ + jbin + jq) = o;
    } else {
        // ---- prep: 64 b x 64 i tile ----
        __shared__ float xs[64][65];
        __shared__ float Xs[K_];
        const int p  = bid - NT_BLOCKS;
        const int b0 = (p & 15) * 64;
        const int i0 = (p >> 4) * 64;
        if (tid < K_) Xs[tid] = Xg[tid];

        // Stage the FULL 64x64 x-tile: 1024 float4s, 256 threads x 4.
        {
            int bb  = tid >> 2;                         // 0..63 (b row)
            int iq0 = (tid & 3) << 2;                   // 0,4,8,12
            #pragma unroll
            for (int r = 0; r < 4; ++r) {
                int iq = iq0 + r * 16;                  // covers 0..63
                float4 v = *(const float4*)(x + (size_t)(b0 + bb) * I_ + i0 + iq);
                xs[bb][iq + 0] = v.x; xs[bb][iq + 1] = v.y;
                xs[bb][iq + 2] = v.z; xs[bb][iq + 3] = v.w;
            }
        }
        __syncthreads();

        const int b  = tid & 63;
        const int ig = tid >> 6;
        const float X0   = Xs[0];
        const float hinv = (float)(K_ - 1) / (Xs[K_ - 1] - X0);
        #pragma unroll 4
        for (int q = 0; q < 16; ++q) {
            int   i  = ig * 16 + q;
            float xv = xs[b][i];                        // conflict-free (stride 65)
            int k = (int)floorf((xv - X0) * hinv);
            k = min(max(k, 0), K_ - 2);
            // exact fixup vs true grid (matches searchsorted side="right",
            // idx clipped to [1,K-1])
            while (k > 0 && xv < Xs[k]) --k;
            while (k < K_ - 2 && xv >= Xs[k + 1]) ++k;
            float x0 = Xs[k], x1 = Xs[k + 1];
            float tt = (xv - x0) / (x1 - x0);           // extrapolates at edges
            // byte offset, jt-independent: i-block + k-row within tile
            int off0 = (i0 + i) * (K_ * J_ * 4) + k * (TJ * 4);
            g_prep[(size_t)(i0 + i) * B_ + b0 + b] =
                make_int4(__float_as_int(1.0f - tt), __float_as_int(tt),
                          off0, off0 + TJ * 4);
        }
    }
}

// ---------------------------------------------------------------------------
// main_kernel: grid (16,2,8) = 256 CTAs, 512 threads, 16 warps x 4 b.
// R13: TARGETED prefetch — each warp prefetches exactly the 8 rows (32 x
// 128B lines = 32 lanes) it will read NEXT iteration, addresses taken from
// s_prep[ii+1]. One LDS + one prefetch.global.L1 per lane per iteration.
// (R12's whole-tile prefetch was 16x redundant across bt-CTAs and tripled
// L2 traffic, 43.9% L2 -> regression.)
// Prep slab (32KB) staged to smem once; no prep LDGs in the mainloop.
// Last CTA per (bt,jt) reduces the ISPL=8 partials (deterministic order).
// ---------------------------------------------------------------------------
__global__ void __launch_bounds__(NTHR, 2)
main_kernel(float* __restrict__ outp) {
    __shared__ int4 s_prep[IPC][TB];           // 32 KB
    __shared__ unsigned int s_last;

    const int bt = blockIdx.x;                 // 0..15
    const int jt = blockIdx.y;                 // 0..1
    const int it = blockIdx.z;                 // 0..7
    const int i0 = it * IPC;
    const int j0 = jt * TJ;
    const int b0 = bt * TB;

    const int w    = threadIdx.x >> 5;         // 0..15
    const int lane = threadIdx.x & 31;
    const int wb   = w * BPW;                  // warp's first local b

    // ---- stage prep slab: 2048 int4s, 512 threads x 4 coalesced rounds ----
    {
        const int4* gp = g_prep + (size_t)i0 * B_ + b0;
        #pragma unroll
        for (int r = 0; r < (IPC * TB) / NTHR; ++r) {
            int flat = threadIdx.x + r * NTHR;
            int ii = flat >> 6;                // / TB
            int b  = flat & (TB - 1);
            s_prep[ii][b] = gp[(size_t)ii * B_ + b];
        }
    }
    __syncthreads();

    // acc[bb] = 4 floats (2 packed f32x2) per b
    unsigned long long accA[BPW], accB[BPW];
    #pragma unroll
    for (int q = 0; q < BPW; ++q) { accA[q] = 0ULL; accB[q] = 0ULL; }

    // pfbase: start of this jt's tile space; prep offsets add i/k terms
    const char* pfbase = (const char*)g_Yt + (size_t)jt * TILE_BYTES;
    const char* ybase  = pfbase + (size_t)lane * 16;

    // prefetch-lane decode: row = lane>>2 (0..7) -> bb = row>>1, sel = row&1
    const int pf_bb   = lane >> 3;             // 0..3 (b within warp group)
    const int pf_sel  = (lane >> 2) & 1;       // row 0 or 1 of the pair
    const int pf_part = (lane & 3) * 128;      // which 128B line of the 512B row

    for (int ii = 0; ii < IPC; ++ii) {
        // targeted L1 prefetch of next iteration's rows (1 pf instr/lane)
        if (ii + 1 < IPC) {
            int4 pn = s_prep[ii + 1][wb + pf_bb];      // 4 distinct addrs/warp
            int offn = pf_sel ? pn.w : pn.z;
            asm volatile("prefetch.global.L1 [%0];"
                         :: "l"(pfbase + offn + pf_part));
        }

        int4 p[BPW];
        #pragma unroll
        for (int bb = 0; bb < BPW; ++bb) p[bb] = s_prep[ii][wb + bb];   // LDS.128 broadcast
        #pragma unroll
        for (int bb = 0; bb < BPW; ++bb) {
            ulonglong2 y0 = *(const ulonglong2*)(ybase + p[bb].z);      // LDG.128
            ulonglong2 y1 = *(const ulonglong2*)(ybase + p[bb].w);      // LDG.128
            unsigned long long W0, W1;
            asm("mov.b64 %0, {%1, %1};" : "=l"(W0) : "r"(p[bb].x));
            asm("mov.b64 %0, {%1, %1};" : "=l"(W1) : "r"(p[bb].y));
            asm("fma.rn.f32x2 %0, %1, %2, %0;" : "+l"(accA[bb]) : "l"(W0), "l"(y0.x));
            asm("fma.rn.f32x2 %0, %1, %2, %0;" : "+l"(accB[bb]) : "l"(W0), "l"(y0.y));
            asm("fma.rn.f32x2 %0, %1, %2, %0;" : "+l"(accA[bb]) : "l"(W1), "l"(y1.x));
            asm("fma.rn.f32x2 %0, %1, %2, %0;" : "+l"(accB[bb]) : "l"(W1), "l"(y1.y));
        }
    }

    // write partial sums (deterministic, per-it slice), STG.128
    float* part = (float*)g_part4 + (size_t)it * (B_ * J_);
    const int bw = b0 + wb;
    #pragma unroll
    for (int bb = 0; bb < BPW; ++bb) {
        ulonglong2 v; v.x = accA[bb]; v.y = accB[bb];
        *(ulonglong2*)(part + (size_t)(bw + bb) * J_ + j0 + 4 * lane) = v;
    }

    // ---- fused last-block reduction over the ISPL partials ----
    __threadfence();                           // publish partials (release)
    if (threadIdx.x == 0) {
        unsigned int old = atomicAdd(&g_cnt[bt * NJT + jt], 1u);
        s_last = (old == ISPL - 1) ? 1u : 0u;
    }
    __syncthreads();
    if (s_last) {
        __threadfence();                       // acquire other CTAs' partials
        if (threadIdx.x == 0) g_cnt[bt * NJT + jt] = 0;   // self-reset for replay
        const int stride = B_ * J_ / 4;
        for (int t = threadIdx.x; t < TB * TJ / 4; t += NTHR) {
            int row = t >> 5;                  // 0..63   (TJ/4 = 32)
            int c4  = t & 31;
            size_t idx = (((size_t)(b0 + row) * J_ + j0) >> 2) + c4;
            float4 p0 = g_part4[idx];
            float4 p1 = g_part4[idx + stride];
            float4 p2 = g_part4[idx + 2 * stride];
            float4 p3 = g_part4[idx + 3 * stride];
            float4 p4 = g_part4[idx + 4 * stride];
            float4 p5 = g_part4[idx + 5 * stride];
            float4 p6 = g_part4[idx + 6 * stride];
            float4 p7 = g_part4[idx + 7 * stride];
            float4 r;
            r.x = ((p0.x + p1.x) + (p2.x + p3.x)) + ((p4.x + p5.x) + (p6.x + p7.x));
            r.y = ((p0.y + p1.y) + (p2.y + p3.y)) + ((p4.y + p5.y) + (p6.y + p7.y));
            r.z = ((p0.z + p1.z) + (p2.z + p3.z)) + ((p4.z + p5.z) + (p6.z + p7.z));
            r.w = ((p0.w + p1.w) + (p2.w + p3.w)) + ((p4.w + p5.w) + (p6.w + p7.w));
            ((float4*)outp)[idx] = r;
        }
    }
}

// ---------------------------------------------------------------------------
extern "C" void kernel_launch(void* const* d_in, const int* in_sizes, int n_in,
                              void* d_out, int out_size) {
    const float* x  = (const float*)d_in[0];   // [B, I]
    const float* Xg = (const float*)d_in[1];   // [K]
    const float* Y  = (const float*)d_in[2];   // [I, J, K]
    float* out = (float*)d_out;                // [B, J]

    pre_kernel<<<NT_BLOCKS + NP_BLOCKS, 256>>>(x, Xg, Y);
    main_kernel<<<dim3(NBT, NJT, ISPL), NTHR>>>(out);
}

// round 14
// speedup vs baseline: 1.2111x; 1.2111x over previous
#include <cuda_runtime.h>

// Problem constants
#define B_   1024
#define I_   256
#define J_   256
#define K_   64

// Tiling
#define TB   64            // b per CTA
#define TJ   128           // j per CTA (4 floats per lane, LDG.128 rows)
#define ISPL 8             // i-splits (keeps grid at 256 CTAs)
#define IPC  (I_ / ISPL)   // 32 iterations per CTA
#define NTHR 512           // 16 warps, 4 b per warp
#define BPW  4
#define NBT  (B_ / TB)     // 16
#define NJT  (J_ / TJ)     // 2

// Static device scratch (no allocations allowed)
// Yt flat layout (R11): [i][k][j]
__device__ float        g_Yt[I_ * K_ * J_];             // 16.8 MB
__device__ int2         g_prep[I_ * B_];                // [i][b]: {w0, off0B}  (R14: int2)
__device__ float4       g_part4[ISPL * B_ * J_ / 4];    // i-split partials (8 MB)
__device__ unsigned int g_cnt[NBT * NJT];               // last-block counters (self-resetting)

#define NT_BLOCKS (I_ * (J_ / 32) * (K_ / 32))          // 4096 transpose blocks
#define NP_BLOCKS ((B_ / 64) * (I_ / 64))               // 64 prep blocks

// ---------------------------------------------------------------------------
// pre_kernel: fused Y-transpose + interval/weight prep (disjoint block ranges
// run concurrently). Transpose: 32x32 fp32 tiles via smem, coalesced both
// sides, conflict-free smem (stride 33). Prep: smem-transposed x reads so both
// the x loads and the g_prep stores are coalesced.
// R14: prep entry is int2 {w0 = 1-t, off0 = absolute byte offset of row k0};
// consumer derives w1 = 1-w0 and row k0+1 via immediate +J*4 bytes.
// ---------------------------------------------------------------------------
__global__ void __launch_bounds__(256) pre_kernel(const float* __restrict__ x,
                                                  const float* __restrict__ Xg,
                                                  const float* __restrict__ Y) {
    const int bid = blockIdx.x;
    const int tid = threadIdx.x;

    if (bid < NT_BLOCKS) {
        // ---- transpose Y[i][j][k] -> Yt[i][k][j], one 32x32 tile ----
        __shared__ float s[32][33];
        const int i    = bid >> 4;
        const int rest = bid & 15;
        const int jb   = (rest >> 1) * 32;
        const int kb   = (rest & 1) * 32;
        const float* src = Y + (size_t)i * (J_ * K_);

        int jj = tid >> 3, kq = (tid & 7) << 2;
        float4 v = *(const float4*)(src + (size_t)(jb + jj) * K_ + kb + kq);
        s[jj][kq + 0] = v.x; s[jj][kq + 1] = v.y;
        s[jj][kq + 2] = v.z; s[jj][kq + 3] = v.w;
        __syncthreads();

        int k = tid >> 3, jq = (tid & 7) << 2;
        float4 o = make_float4(s[jq + 0][k], s[jq + 1][k], s[jq + 2][k], s[jq + 3][k]);
        *(float4*)(g_Yt + (size_t)i * (K_ * J_) + (size_t)(kb + k) * J_ + jb + jq) = o;
    } else {
        // ---- prep: 64 b x 64 i tile ----
        __shared__ float xs[64][65];
        __shared__ float Xs[K_];
        const int p  = bid - NT_BLOCKS;
        const int b0 = (p & 15) * 64;
        const int i0 = (p >> 4) * 64;
        if (tid < K_) Xs[tid] = Xg[tid];

        // Stage the FULL 64x64 x-tile: 1024 float4s, 256 threads x 4.
        {
            int bb  = tid >> 2;                         // 0..63 (b row)
            int iq0 = (tid & 3) << 2;                   // 0,4,8,12
            #pragma unroll
            for (int r = 0; r < 4; ++r) {
                int iq = iq0 + r * 16;                  // covers 0..63
                float4 v = *(const float4*)(x + (size_t)(b0 + bb) * I_ + i0 + iq);
                xs[bb][iq + 0] = v.x; xs[bb][iq + 1] = v.y;
                xs[bb][iq + 2] = v.z; xs[bb][iq + 3] = v.w;
            }
        }
        __syncthreads();

        const int b  = tid & 63;
        const int ig = tid >> 6;
        const float X0   = Xs[0];
        const float hinv = (float)(K_ - 1) / (Xs[K_ - 1] - X0);
        #pragma unroll 4
        for (int q = 0; q < 16; ++q) {
            int   i  = ig * 16 + q;
            float xv = xs[b][i];                        // conflict-free (stride 65)
            int k = (int)floorf((xv - X0) * hinv);
            k = min(max(k, 0), K_ - 2);
            // exact fixup vs true grid (matches searchsorted side="right",
            // idx clipped to [1,K-1])
            while (k > 0 && xv < Xs[k]) --k;
            while (k < K_ - 2 && xv >= Xs[k + 1]) ++k;
            float x0 = Xs[k], x1 = Xs[k + 1];
            float tt = (xv - x0) / (x1 - x0);           // extrapolates at edges
            int off0 = ((i0 + i) * K_ + k) * (J_ * 4);  // ABSOLUTE byte offset in g_Yt
            g_prep[(size_t)(i0 + i) * B_ + b0 + b] =
                make_int2(__float_as_int(1.0f - tt), off0);
        }
    }
}

// ---------------------------------------------------------------------------
// main_kernel: grid (16,2,8) = 256 CTAs, 512 threads, 16 warps x 4 b.
// R14 vs R11: int2 prep (LDS.64, w1=1-w0, row1 via immediate +1024B) frees
// ~10 regs; #pragma unroll 2 lets ptxas overlap iteration ii+1's LDS/LDGs
// with iteration ii's FMAs (R11 was pinned at the 64-reg occ-2 ceiling with
// zero scheduling slack -> issue 23%, latency-exposed).
// No prefetch (R12/R13 falsified: prefetch.global.L1 always hits L2 on
// sm_103a, tripling L2 traffic).
// Last CTA per (bt,jt) reduces the ISPL=8 partials (deterministic order).
// ---------------------------------------------------------------------------
__global__ void __launch_bounds__(NTHR, 2)
main_kernel(float* __restrict__ outp) {
    __shared__ int2 s_prep[IPC][TB];           // 16 KB
    __shared__ unsigned int s_last;

    const int bt = blockIdx.x;                 // 0..15
    const int jt = blockIdx.y;                 // 0..1
    const int it = blockIdx.z;                 // 0..7
    const int i0 = it * IPC;
    const int j0 = jt * TJ;
    const int b0 = bt * TB;

    const int w    = threadIdx.x >> 5;         // 0..15
    const int lane = threadIdx.x & 31;
    const int wb   = w * BPW;                  // warp's first local b

    // ---- stage prep slab: 2048 int2s, 512 threads x 4 coalesced rounds ----
    {
        const int2* gp = g_prep + (size_t)i0 * B_ + b0;
        #pragma unroll
        for (int r = 0; r < (IPC * TB) / NTHR; ++r) {
            int flat = threadIdx.x + r * NTHR;
            int ii = flat >> 6;                // / TB
            int b  = flat & (TB - 1);
            s_prep[ii][b] = gp[(size_t)ii * B_ + b];
        }
    }
    __syncthreads();

    // acc[bb] = 4 floats (2 packed f32x2) per b
    unsigned long long accA[BPW], accB[BPW];
    #pragma unroll
    for (int q = 0; q < BPW; ++q) { accA[q] = 0ULL; accB[q] = 0ULL; }

    const char* ybase = (const char*)g_Yt + (size_t)(j0 + 4 * lane) * 4;

    #pragma unroll 2
    for (int ii = 0; ii < IPC; ++ii) {
        int2 p[BPW];
        #pragma unroll
        for (int bb = 0; bb < BPW; ++bb) p[bb] = s_prep[ii][wb + bb];   // LDS.64 broadcast
        #pragma unroll
        for (int bb = 0; bb < BPW; ++bb) {
            const char* r0 = ybase + p[bb].y;
            ulonglong2 y0 = *(const ulonglong2*)(r0);                   // LDG.128 row k0
            ulonglong2 y1 = *(const ulonglong2*)(r0 + J_ * 4);          // LDG.128 row k0+1 (imm)
            float w0f = __int_as_float(p[bb].x);
            float w1f = 1.0f - w0f;
            unsigned long long W0, W1;
            asm("mov.b64 %0, {%1, %1};" : "=l"(W0) : "f"(w0f));
            asm("mov.b64 %0, {%1, %1};" : "=l"(W1) : "f"(w1f));
            asm("fma.rn.f32x2 %0, %1, %2, %0;" : "+l"(accA[bb]) : "l"(W0), "l"(y0.x));
            asm("fma.rn.f32x2 %0, %1, %2, %0;" : "+l"(accB[bb]) : "l"(W0), "l"(y0.y));
            asm("fma.rn.f32x2 %0, %1, %2, %0;" : "+l"(accA[bb]) : "l"(W1), "l"(y1.x));
            asm("fma.rn.f32x2 %0, %1, %2, %0;" : "+l"(accB[bb]) : "l"(W1), "l"(y1.y));
        }
    }

    // write partial sums (deterministic, per-it slice), STG.128
    float* part = (float*)g_part4 + (size_t)it * (B_ * J_);
    const int bw = b0 + wb;
    #pragma unroll
    for (int bb = 0; bb < BPW; ++bb) {
        ulonglong2 v; v.x = accA[bb]; v.y = accB[bb];
        *(ulonglong2*)(part + (size_t)(bw + bb) * J_ + j0 + 4 * lane) = v;
    }

    // ---- fused last-block reduction over the ISPL partials ----
    __threadfence();                           // publish partials (release)
    if (threadIdx.x == 0) {
        unsigned int old = atomicAdd(&g_cnt[bt * NJT + jt], 1u);
        s_last = (old == ISPL - 1) ? 1u : 0u;
    }
    __syncthreads();
    if (s_last) {
        __threadfence();                       // acquire other CTAs' partials
        if (threadIdx.x == 0) g_cnt[bt * NJT + jt] = 0;   // self-reset for replay
        const int stride = B_ * J_ / 4;
        for (int t = threadIdx.x; t < TB * TJ / 4; t += NTHR) {
            int row = t >> 5;                  // 0..63   (TJ/4 = 32)
            int c4  = t & 31;
            size_t idx = (((size_t)(b0 + row) * J_ + j0) >> 2) + c4;
            float4 p0 = g_part4[idx];
            float4 p1 = g_part4[idx + stride];
            float4 p2 = g_part4[idx + 2 * stride];
            float4 p3 = g_part4[idx + 3 * stride];
            float4 p4 = g_part4[idx + 4 * stride];
            float4 p5 = g_part4[idx + 5 * stride];
            float4 p6 = g_part4[idx + 6 * stride];
            float4 p7 = g_part4[idx + 7 * stride];
            float4 r;
            r.x = ((p0.x + p1.x) + (p2.x + p3.x)) + ((p4.x + p5.x) + (p6.x + p7.x));
            r.y = ((p0.y + p1.y) + (p2.y + p3.y)) + ((p4.y + p5.y) + (p6.y + p7.y));
            r.z = ((p0.z + p1.z) + (p2.z + p3.z)) + ((p4.z + p5.z) + (p6.z + p7.z));
            r.w = ((p0.w + p1.w) + (p2.w + p3.w)) + ((p4.w + p5.w) + (p6.w + p7.w));
            ((float4*)outp)[idx] = r;
        }
    }
}

// ---------------------------------------------------------------------------
extern "C" void kernel_launch(void* const* d_in, const int* in_sizes, int n_in,
                              void* d_out, int out_size) {
    const float* x  = (const float*)d_in[0];   // [B, I]
    const float* Xg = (const float*)d_in[1];   // [K]
    const float* Y  = (const float*)d_in[2];   // [I, J, K]
    float* out = (float*)d_out;                // [B, J]

    pre_kernel<<<NT_BLOCKS + NP_BLOCKS, 256>>>(x, Xg, Y);
    main_kernel<<<dim3(NBT, NJT, ISPL), NTHR>>>(out);
}